// round 12
// baseline (speedup 1.0000x reference)
#include <cuda_runtime.h>
#include <cstdint>

// hidden_states: [B=32, S=4096, H=768] fp32
// w_start, w_end: [768] fp32
// out: [2, B*S] fp32  (start_logits then end_logits)
//
// cp.async per-warp double-buffered streaming pipeline: MLP decoupled from
// registers, no inter-tile drain. Each warp streams one 3KB row per stage
// into its private smem slice while consuming the previous stage.

static constexpr int H   = 768;
static constexpr int HV  = H / 4;     // 192 float4 per row
static constexpr int VPL = HV / 32;   // 6 float4 per lane per row
static constexpr int THREADS = 256;
static constexpr int WARPS = THREADS / 32;
static constexpr int STAGES = 2;
// dynamic smem: [sa 192][sb 192][buf: WARPS*STAGES*192] float4
static constexpr int SMEM_F4   = 2 * HV + WARPS * STAGES * HV;
static constexpr int SMEM_BYTES = SMEM_F4 * 16;   // 55296 B

__device__ __forceinline__ void cp16(float4* dst_smem, const float4* src) {
    uint32_t d = (uint32_t)__cvta_generic_to_shared(dst_smem);
    asm volatile("cp.async.cg.shared.global [%0], [%1], 16;" :: "r"(d), "l"(src));
}
__device__ __forceinline__ void cp_commit() {
    asm volatile("cp.async.commit_group;");
}
template <int N>
__device__ __forceinline__ void cp_wait() {
    asm volatile("cp.async.wait_group %0;" :: "n"(N));
}

__global__ __launch_bounds__(THREADS)
void dual_dot_kernel(const float4* __restrict__ hs,
                     const float4* __restrict__ ws,
                     const float4* __restrict__ we,
                     float* __restrict__ out,
                     int rows, int total_warps) {
    extern __shared__ float4 smem[];
    float4* sa = smem;
    float4* sb = smem + HV;

    for (int i = threadIdx.x; i < HV; i += THREADS) {
        sa[i] = ws[i];
        sb[i] = we[i];
    }
    __syncthreads();

    const int wid  = (int)(threadIdx.x >> 5);
    const int lane = threadIdx.x & 31;
    const int gw   = blockIdx.x * WARPS + wid;   // global warp id
    float4* buf = smem + 2 * HV + wid * (STAGES * HV);

    // Prefetch first row of this warp's strided sequence.
    if (gw < rows) {
        const float4* src = hs + (size_t)gw * HV;
        #pragma unroll
        for (int j = 0; j < VPL; ++j)
            cp16(&buf[lane + 32 * j], &src[lane + 32 * j]);
    }
    cp_commit();

    int k = 0;
    for (int rcur = gw; rcur < rows; rcur += total_warps, ++k) {
        // Issue next stage's loads before consuming current stage.
        const int rnext = rcur + total_warps;
        if (rnext < rows) {
            const float4* src = hs + (size_t)rnext * HV;
            float4* nb = &buf[((k + 1) & 1) * HV];
            #pragma unroll
            for (int j = 0; j < VPL; ++j)
                cp16(&nb[lane + 32 * j], &src[lane + 32 * j]);
        }
        cp_commit();
        cp_wait<1>();          // stage k landed; stage k+1 still in flight

        const float4* hb = &buf[(k & 1) * HV];
        float s = 0.0f, e = 0.0f;
        #pragma unroll
        for (int j = 0; j < VPL; ++j) {
            const int idx = lane + 32 * j;
            float4 h = hb[idx];
            float4 a = sa[idx];
            float4 b = sb[idx];
            s = fmaf(h.x, a.x, s); s = fmaf(h.y, a.y, s);
            s = fmaf(h.z, a.z, s); s = fmaf(h.w, a.w, s);
            e = fmaf(h.x, b.x, e); e = fmaf(h.y, b.y, e);
            e = fmaf(h.z, b.z, e); e = fmaf(h.w, b.w, e);
        }

        #pragma unroll
        for (int o = 16; o > 0; o >>= 1) {
            s += __shfl_xor_sync(0xffffffffu, s, o);
            e += __shfl_xor_sync(0xffffffffu, e, o);
        }

        if (lane == 0) {
            out[rcur]        = s;   // start_logits
            out[rows + rcur] = e;   // end_logits
        }
    }
}

extern "C" void kernel_launch(void* const* d_in, const int* in_sizes, int n_in,
                              void* d_out, int out_size) {
    const float4* hs = (const float4*)d_in[0];
    const float4* ws = (const float4*)d_in[1];
    const float4* we = (const float4*)d_in[2];
    float* out       = (float*)d_out;

    const int rows = in_sizes[0] / H;   // 131072

    static bool attr_set = false;       // host-side config, not kernel state
    if (!attr_set) {
        cudaFuncSetAttribute(dual_dot_kernel,
                             cudaFuncAttributeMaxDynamicSharedMemorySize,
                             SMEM_BYTES);
        attr_set = true;
    }

    // 4 blocks/SM resident (smem-limited); grid-stride covers all rows.
    const int blocks = 4 * 148;
    const int total_warps = blocks * WARPS;

    dual_dot_kernel<<<blocks, THREADS, SMEM_BYTES>>>(hs, ws, we, out,
                                                     rows, total_warps);
}

// round 13
// speedup vs baseline: 1.1490x; 1.1490x over previous
#include <cuda_runtime.h>

// hidden_states: [B=32, S=4096, H=768] fp32
// w_start, w_end: [768] fp32
// out: [2, B*S] fp32  (start_logits then end_logits)
//
// R9 (59.8us) won via front-batched 12x LDG.128, but ptxas clipped the live
// batch to regs=40 (<48 needed). This round: identical structure with
// __launch_bounds__(256,3) -> ~84-reg budget so the FULL 12-load batch
// stays live. occ ~24 warps/SM x 6KB in flight each.

static constexpr int H   = 768;
static constexpr int HV  = H / 4;      // 192 float4 per row
static constexpr int VPL = HV / 32;    // 6 float4 per lane per row
static constexpr int R   = 2;          // rows per warp
static constexpr int THREADS = 256;    // 8 warps/block

__global__ __launch_bounds__(THREADS, 3)   // allow ~84 regs/thread
void dual_dot_kernel(const float4* __restrict__ hs,
                     const float4* __restrict__ ws,
                     const float4* __restrict__ we,
                     float* __restrict__ out,
                     int rows) {
    // Weights in shared memory: 2 x 192 float4 = 6 KB, conflict-free lane-indexed reads.
    __shared__ float4 sa[HV];
    __shared__ float4 sb[HV];
    for (int i = threadIdx.x; i < HV; i += THREADS) {
        sa[i] = ws[i];
        sb[i] = we[i];
    }
    __syncthreads();

    const int warp = (int)((blockIdx.x * blockDim.x + threadIdx.x) >> 5);
    const int lane = threadIdx.x & 31;
    const int row0 = warp * R;
    if (row0 >= rows) return;

    const float4* __restrict__ p = hs + (size_t)row0 * HV;

    float s[R], e[R];
    #pragma unroll
    for (int r = 0; r < R; ++r) { s[r] = 0.0f; e[r] = 0.0f; }

    // Front-batch all R*VPL = 12 independent LDG.128s, then consume.
    float4 h[R][VPL];
    #pragma unroll
    for (int j = 0; j < VPL; ++j) {
        #pragma unroll
        for (int r = 0; r < R; ++r) {
            h[r][j] = __ldcs(&p[(size_t)r * HV + lane + 32 * j]);
        }
    }

    #pragma unroll
    for (int j = 0; j < VPL; ++j) {
        const int idx = lane + 32 * j;
        float4 a = sa[idx];
        float4 b = sb[idx];
        #pragma unroll
        for (int r = 0; r < R; ++r) {
            s[r] = fmaf(h[r][j].x, a.x, s[r]);
            s[r] = fmaf(h[r][j].y, a.y, s[r]);
            s[r] = fmaf(h[r][j].z, a.z, s[r]);
            s[r] = fmaf(h[r][j].w, a.w, s[r]);
            e[r] = fmaf(h[r][j].x, b.x, e[r]);
            e[r] = fmaf(h[r][j].y, b.y, e[r]);
            e[r] = fmaf(h[r][j].z, b.z, e[r]);
            e[r] = fmaf(h[r][j].w, b.w, e[r]);
        }
    }

    #pragma unroll
    for (int r = 0; r < R; ++r) {
        #pragma unroll
        for (int o = 16; o > 0; o >>= 1) {
            s[r] += __shfl_xor_sync(0xffffffffu, s[r], o);
            e[r] += __shfl_xor_sync(0xffffffffu, e[r], o);
        }
    }

    if (lane == 0) {
        #pragma unroll
        for (int r = 0; r < R; ++r) {
            out[row0 + r]        = s[r];   // start_logits
            out[rows + row0 + r] = e[r];   // end_logits
        }
    }
}

extern "C" void kernel_launch(void* const* d_in, const int* in_sizes, int n_in,
                              void* d_out, int out_size) {
    const float4* hs = (const float4*)d_in[0];
    const float4* ws = (const float4*)d_in[1];
    const float4* we = (const float4*)d_in[2];
    float* out       = (float*)d_out;

    const int rows = in_sizes[0] / H;                     // 131072
    const int rows_per_block = (THREADS / 32) * R;        // 16
    const int blocks = (rows + rows_per_block - 1) / rows_per_block;

    dual_dot_kernel<<<blocks, THREADS>>>(hs, ws, we, out, rows);
}